// round 2
// baseline (speedup 1.0000x reference)
#include <cuda_runtime.h>
#include <math_constants.h>

// Problem constants
#define Bsz   64
#define Lseq  2048
#define Dm    512
#define NC1   8              // chunks for mean pass
#define TOK1  (Lseq / NC1)   // 256 tokens per chunk
#define NC2   8              // chunks for attention pass
#define TOK2  (Lseq / NC2)   // 256 tokens per chunk
#define WARPS_C 8            // warps per block in kernel C
#define TOKW  (TOK2 / WARPS_C) // 32 tokens per warp

// Scratch (static device globals — no allocation)
__device__ float g_hpart[Bsz * NC1 * Dm];     // partial sums for h
__device__ float g_v[Bsz * Dm];               // v = W_b @ h
__device__ float g_m[Bsz * NC2];              // per-chunk softmax max
__device__ float g_dsum[Bsz * NC2];           // per-chunk softmax denom
__device__ float g_ct[Bsz * NC2 * Dm];        // per-chunk weighted sums

// ---------------------------------------------------------------------------
// Kernel A: partial sums of embedding rows -> g_hpart[b, chunk, col]
// grid (Bsz, NC1), 512 threads, thread = column
// ---------------------------------------------------------------------------
__global__ __launch_bounds__(Dm) void k_hpart(const int* __restrict__ tokens,
                                              const float* __restrict__ emb) {
    const int b = blockIdx.x, c = blockIdx.y;
    const int col = threadIdx.x;

    __shared__ int s_tok[TOK1];
    for (int i = threadIdx.x; i < TOK1; i += Dm)
        s_tok[i] = tokens[b * Lseq + c * TOK1 + i] + 1;
    __syncthreads();

    float acc = 0.0f;
#pragma unroll 8
    for (int l = 0; l < TOK1; ++l) {
        long row = (long)s_tok[l];
        acc += __ldg(emb + row * Dm + col);
    }
    g_hpart[(b * NC1 + c) * Dm + col] = acc;
}

// ---------------------------------------------------------------------------
// Kernel B: reduce h, then v[b,d] = sum_e W_b[d,e] * h[b,e]
// grid (Bsz), 512 threads, thread = output d
// ---------------------------------------------------------------------------
__global__ __launch_bounds__(Dm) void k_v(const float* __restrict__ W) {
    const int b = blockIdx.x;
    const int d = threadIdx.x;

    __shared__ float s_h[Dm];
    float hacc = 0.0f;
#pragma unroll
    for (int c = 0; c < NC1; ++c)
        hacc += g_hpart[(b * NC1 + c) * Dm + d];
    s_h[d] = hacc * (1.0f / (float)Lseq);
    __syncthreads();

    const float4* Wrow = (const float4*)(W + (long)d * Dm);
    float acc = 0.0f;
#pragma unroll 8
    for (int e4 = 0; e4 < Dm / 4; ++e4) {
        float4 w = __ldg(Wrow + e4);
        acc += w.x * s_h[e4 * 4 + 0] + w.y * s_h[e4 * 4 + 1]
             + w.z * s_h[e4 * 4 + 2] + w.w * s_h[e4 * 4 + 3];
    }
    g_v[b * Dm + d] = acc;
}

// ---------------------------------------------------------------------------
// Kernel C: fused score + online softmax + weighted accumulation, per chunk.
// grid (Bsz, NC2), 256 threads = 8 warps, warp handles TOKW tokens.
// Lane owns 16 columns: col = 128*i + 4*lane + j  (i in [0,4), j in [0,4))
// One embedding-row read serves BOTH the score dot and the ct accumulation.
// ---------------------------------------------------------------------------
__global__ __launch_bounds__(32 * WARPS_C) void k_attn(const int* __restrict__ tokens,
                                                       const float* __restrict__ emb) {
    const int b = blockIdx.x, c = blockIdx.y;
    const int warp = threadIdx.x >> 5;
    const int lane = threadIdx.x & 31;

    __shared__ int   s_tok[TOK2];
    __shared__ float s_m[WARPS_C], s_d[WARPS_C];
    __shared__ float s_ct[WARPS_C][Dm];   // 16 KB

    for (int i = threadIdx.x; i < TOK2; i += 32 * WARPS_C)
        s_tok[i] = tokens[b * Lseq + c * TOK2 + i] + 1;

    // preload this lane's 16 v values
    float4 vr[4];
    const float4* vbase = (const float4*)(g_v + b * Dm);
#pragma unroll
    for (int i = 0; i < 4; ++i)
        vr[i] = vbase[i * (Dm / 16) + lane];   // Dm/16 = 32 float4 per 128-col group... (see note)
    // NOTE: layout: group i covers cols [128*i, 128*i+128); within group, lane*4+j.
    // float4 index within group = lane; group stride in float4 units = 128/4 = 32.
    __syncthreads();

    float m = -CUDART_INF_F;
    float dsum = 0.0f;
    float4 acc[4];
#pragma unroll
    for (int i = 0; i < 4; ++i) acc[i] = make_float4(0.f, 0.f, 0.f, 0.f);

    for (int t = 0; t < TOKW; ++t) {
        long row = (long)s_tok[warp * TOKW + t];
        const float4* e = (const float4*)(emb + row * Dm);
        float4 ev[4];
#pragma unroll
        for (int i = 0; i < 4; ++i)
            ev[i] = __ldg(e + i * 32 + lane);   // coalesced: 32 lanes x 16B contiguous

        float s = 0.0f;
#pragma unroll
        for (int i = 0; i < 4; ++i)
            s += ev[i].x * vr[i].x + ev[i].y * vr[i].y
               + ev[i].z * vr[i].z + ev[i].w * vr[i].w;
        // warp-wide sum (butterfly -> all lanes hold total)
#pragma unroll
        for (int off = 16; off > 0; off >>= 1)
            s += __shfl_xor_sync(0xffffffffu, s, off);

        float mnew  = fmaxf(m, s);
        float scale = __expf(m - mnew);   // exp(-inf)=0 on first iter
        float p     = __expf(s - mnew);
        dsum = dsum * scale + p;
#pragma unroll
        for (int i = 0; i < 4; ++i) {
            acc[i].x = acc[i].x * scale + p * ev[i].x;
            acc[i].y = acc[i].y * scale + p * ev[i].y;
            acc[i].z = acc[i].z * scale + p * ev[i].z;
            acc[i].w = acc[i].w * scale + p * ev[i].w;
        }
        m = mnew;
    }

    // deposit per-warp partials in shared
    if (lane == 0) { s_m[warp] = m; s_d[warp] = dsum; }
#pragma unroll
    for (int i = 0; i < 4; ++i) {
        int col = 128 * i + 4 * lane;
        s_ct[warp][col + 0] = acc[i].x;
        s_ct[warp][col + 1] = acc[i].y;
        s_ct[warp][col + 2] = acc[i].z;
        s_ct[warp][col + 3] = acc[i].w;
    }
    __syncthreads();

    // block-level merge of the 8 warp partials
    float M = -CUDART_INF_F;
#pragma unroll
    for (int w = 0; w < WARPS_C; ++w) M = fmaxf(M, s_m[w]);

    float wexp[WARPS_C];
#pragma unroll
    for (int w = 0; w < WARPS_C; ++w) wexp[w] = __expf(s_m[w] - M);

    // each thread merges 2 columns
    for (int col = threadIdx.x; col < Dm; col += 32 * WARPS_C) {
        float cts = 0.0f;
#pragma unroll
        for (int w = 0; w < WARPS_C; ++w)
            cts += wexp[w] * s_ct[w][col];
        g_ct[(b * NC2 + c) * Dm + col] = cts;
    }
    if (threadIdx.x == 0) {
        float D = 0.0f;
#pragma unroll
        for (int w = 0; w < WARPS_C; ++w) D += wexp[w] * s_d[w];
        g_m[b * NC2 + c]    = M;
        g_dsum[b * NC2 + c] = D;
    }
}

// ---------------------------------------------------------------------------
// Kernel D: merge the NC2 chunk partials -> output ct[b, col]
// grid (Bsz), 512 threads
// ---------------------------------------------------------------------------
__global__ __launch_bounds__(Dm) void k_merge(float* __restrict__ out) {
    const int b = blockIdx.x;
    const int col = threadIdx.x;

    float M = -CUDART_INF_F;
#pragma unroll
    for (int c = 0; c < NC2; ++c) M = fmaxf(M, g_m[b * NC2 + c]);

    float denom = 0.0f;
    float r = 0.0f;
#pragma unroll
    for (int c = 0; c < NC2; ++c) {
        float e = __expf(g_m[b * NC2 + c] - M);
        denom += e * g_dsum[b * NC2 + c];
        r     += e * g_ct[(b * NC2 + c) * Dm + col];
    }
    out[b * Dm + col] = r / denom;
}

// ---------------------------------------------------------------------------
extern "C" void kernel_launch(void* const* d_in, const int* in_sizes, int n_in,
                              void* d_out, int out_size) {
    const int*   tokens = (const int*)d_in[0];
    const float* emb    = (const float*)d_in[1];
    const float* W_b    = (const float*)d_in[2];
    // d_in[3] = max_len (compile-time constant Lseq)
    float* out = (float*)d_out;

    k_hpart<<<dim3(Bsz, NC1), Dm>>>(tokens, emb);
    k_v<<<Bsz, Dm>>>(W_b);
    k_attn<<<dim3(Bsz, NC2), 32 * WARPS_C>>>(tokens, emb);
    k_merge<<<Bsz, Dm>>>(out);
}